// round 11
// baseline (speedup 1.0000x reference)
#include <cuda_runtime.h>
#include <cuda_bf16.h>
#include <cstdint>
#include <cstddef>

// Problem: VQ-VAE quantizer
// inputs: (32, 64, 64, 64) f32 NCHW ; emb_weight: (512, 64) f32
// Outputs (f32): loss(1) | quantized(8388608) | encoding_indices(131072) | perplexity(1) | codes(131072)
#define NB   32
#define NC   64
#define NHW  4096
#define NROW 131072
#define NK   512

#define OFF_LOSS  0
#define OFF_Q     1
#define OFF_IDX   8388609
#define OFF_PERP  8519681
#define OFF_CODES 8519682

#define THETA 0.01f

// ---------------------------------------------------------------------------
// PTX helpers — ONLY baseline (non-arch-specific) instructions:
// ldmatrix (sm_75+), mma.sync bf16 (sm_80+). No tcgen05 (needs sm_103a target).
// ---------------------------------------------------------------------------
__device__ __forceinline__ uint32_t smem_to_u32(const void* p) {
    uint32_t a;
    asm("{ .reg .u64 t; cvta.to.shared.u64 t, %1; cvt.u32.u64 %0, t; }" : "=r"(a) : "l"(p));
    return a;
}

#define LDSM_X4(r, a) \
    asm volatile("ldmatrix.sync.aligned.m8n8.x4.shared.b16 {%0,%1,%2,%3}, [%4];" \
        : "=r"((r)[0]), "=r"((r)[1]), "=r"((r)[2]), "=r"((r)[3]) : "r"(a))
#define LDSM_X2(r, a) \
    asm volatile("ldmatrix.sync.aligned.m8n8.x2.shared.b16 {%0,%1}, [%2];" \
        : "=r"((r)[0]), "=r"((r)[1]) : "r"(a))
#define MMA16816(d, a, b) \
    asm volatile("mma.sync.aligned.m16n8k16.row.col.f32.bf16.bf16.f32 " \
        "{%0,%1,%2,%3}, {%4,%5,%6,%7}, {%8,%9}, {%0,%1,%2,%3};" \
        : "+f"((d)[0]), "+f"((d)[1]), "+f"((d)[2]), "+f"((d)[3]) \
        : "r"((a)[0]), "r"((a)[1]), "r"((a)[2]), "r"((a)[3]), \
          "r"((b)[0]), "r"((b)[1]))

// ---------------------------------------------------------------------------
// Scratch
// ---------------------------------------------------------------------------
__device__ int            g_idx[NROW];
__device__ float          g_counts[NK];
__device__ float          g_hn[NK];          // 0.5 * ||e||^2
__device__ float          g_rowd[NROW];      // per-row ||x - e_best||^2 (fp32)
__device__ int            g_flaglist[NROW];
__device__ int            g_nflag;
__device__ __nv_bfloat16  g_ehi[NK * NC];    // codebook bf16 hi, K-major
__device__ __nv_bfloat16  g_elo[NK * NC];    // codebook bf16 lo (residual)

// SMEM layout (bytes). Row stride 144 B = 9 x 16B units (odd) ->
// ldmatrix 8-row access hits 8 distinct bank groups: conflict-free.
#define RSTRIDE   144
#define SM_AHI    0                       // 128 x 144  = 18432
#define SM_ALO    18432                   // 128 x 144
#define SM_BHI    36864                   // 512 x 144  = 73728
#define SM_BLO    110592                  // 512 x 144
#define SM_HN     184320                  // 512 f32    = 2048
#define SM_M1     186368                  // 8 x 128 f32
#define SM_M2     190464
#define SM_MI     194560
#define SM_TOTAL  198656

// ---------------------------------------------------------------------------
// Kernel 0: init — half-norms, bf16 hi/lo codebook, zero counts/flags
// ---------------------------------------------------------------------------
__global__ void vq_init(const float* __restrict__ emb) {
    int t = threadIdx.x;               // 512 threads
    const float4* e = (const float4*)(emb + t * NC);
    float s = 0.f;
#pragma unroll
    for (int i = 0; i < 16; i++) {
        float4 v = e[i];
        s += v.x * v.x + v.y * v.y + v.z * v.z + v.w * v.w;
    }
    g_hn[t] = 0.5f * s;
    g_counts[t] = 0.f;
    if (t == 0) g_nflag = 0;
    for (int i = t; i < NK * NC; i += 512) {
        float v = emb[i];
        __nv_bfloat16 h = __float2bfloat16(v);
        g_ehi[i] = h;
        g_elo[i] = __float2bfloat16(v - __bfloat162float(h));
    }
}

// ---------------------------------------------------------------------------
// Kernel 1: mma.sync argmin. CTA = 128 rows x 512 codes, 256 threads (8 warps).
// Warp w owns codes [w*64, w*64+64) for ALL 128 rows (B frags reused across m).
// bf16 hi/lo split: D = xh*eh + xh*el + xl*eh (fp32 accum in registers).
// ---------------------------------------------------------------------------
__global__ void __launch_bounds__(256, 1)
vq_argmin(const float* __restrict__ x_in, const float* __restrict__ emb) {
    extern __shared__ char smem[];
    const uint32_t sb = smem_to_u32(smem);
    float* hn_s = (float*)(smem + SM_HN);
    float* m1   = (float*)(smem + SM_M1);
    float* m2   = (float*)(smem + SM_M2);
    int*   mi   = (int*)  (smem + SM_MI);

    const int tid  = threadIdx.x;
    const int w    = tid >> 5;
    const int lane = tid & 31;
    const int n0   = blockIdx.x * 128;
    const int b    = n0 >> 12;
    const int hw0  = n0 & 4095;

    // ---- prologue: x tile -> A hi/lo (row m, col c; 144B row stride)
    const float* xbase = x_in + (size_t)b * (NC * NHW) + hw0;
    for (int i = tid; i < 64 * 128; i += 256) {
        int c = i >> 7, m = i & 127;                    // coalesced over m
        float v = xbase[(size_t)c * NHW + m];
        __nv_bfloat16 h = __float2bfloat16(v);
        __nv_bfloat16 l = __float2bfloat16(v - __bfloat162float(h));
        *(__nv_bfloat16*)(smem + SM_AHI + m * RSTRIDE + c * 2) = h;
        *(__nv_bfloat16*)(smem + SM_ALO + m * RSTRIDE + c * 2) = l;
    }
    // ---- codebook hi/lo -> B tiles (row = code, 144B stride), 4B words
    {
        const uint32_t* ehi = (const uint32_t*)g_ehi;
        const uint32_t* elo = (const uint32_t*)g_elo;
        for (int i = tid; i < NK * NC / 2; i += 256) {
            int code = i >> 5, cw = i & 31;
            *(uint32_t*)(smem + SM_BHI + code * RSTRIDE + cw * 4) = ehi[i];
            *(uint32_t*)(smem + SM_BLO + code * RSTRIDE + cw * 4) = elo[i];
        }
    }
    for (int i = tid; i < NK; i += 256) hn_s[i] = g_hn[i];
    __syncthreads();

    // ---- main: 4 passes of 32 rows (2 m16-tiles), 3 splits, 4 k16-steps
    const uint32_t a_lane_off = (uint32_t)((lane & 15) * RSTRIDE + (lane >> 4) * 16);
    const uint32_t b_lane_off = (uint32_t)((w * 64 + (lane & 7)) * RSTRIDE + ((lane >> 3) & 1) * 16);

    for (int mt2 = 0; mt2 < 4; mt2++) {
        float acc[2][8][4];
#pragma unroll
        for (int p = 0; p < 2; p++)
#pragma unroll
            for (int nt = 0; nt < 8; nt++)
#pragma unroll
                for (int c = 0; c < 4; c++) acc[p][nt][c] = 0.f;

#pragma unroll
        for (int s = 0; s < 3; s++) {
            const uint32_t ab = sb + (s == 2 ? SM_ALO : SM_AHI) + (uint32_t)(mt2 * 32 * RSTRIDE) + a_lane_off;
            const uint32_t bb = sb + (s == 1 ? SM_BLO : SM_BHI) + b_lane_off;
#pragma unroll
            for (int k = 0; k < 4; k++) {
                uint32_t a0[4], a1[4];
                LDSM_X4(a0, ab + k * 32);
                LDSM_X4(a1, ab + 16 * RSTRIDE + k * 32);
#pragma unroll
                for (int nt = 0; nt < 8; nt++) {
                    uint32_t bf[2];
                    LDSM_X2(bf, bb + (uint32_t)(nt * 8 * RSTRIDE) + k * 32);
                    MMA16816(acc[0][nt], a0, bf);
                    MMA16816(acc[1][nt], a1, bf);
                }
            }
        }

        // ---- epilogue for rows [mt2*32, mt2*32+32)
#pragma unroll
        for (int p = 0; p < 2; p++) {
#pragma unroll
            for (int h = 0; h < 2; h++) {
                int row = mt2 * 32 + p * 16 + h * 8 + (lane >> 2);
                float bv1 = -3.4e38f, bv2 = -3.4e38f;
                int bi = 0;
#pragma unroll
                for (int nt = 0; nt < 8; nt++) {
                    int code = w * 64 + nt * 8 + 2 * (lane & 3);
                    float v0 = acc[p][nt][h * 2 + 0] - hn_s[code];
                    float v1 = acc[p][nt][h * 2 + 1] - hn_s[code + 1];
                    if (v0 > bv1) { bv2 = bv1; bv1 = v0; bi = code; }
                    else if (v0 > bv2) bv2 = v0;
                    if (v1 > bv1) { bv2 = bv1; bv1 = v1; bi = code + 1; }
                    else if (v1 > bv2) bv2 = v1;
                }
                // quad reduce (lanes differing in bits 0,1 cover the 8 cols)
#pragma unroll
                for (int off = 1; off <= 2; off <<= 1) {
                    float o1 = __shfl_xor_sync(0xffffffffu, bv1, off);
                    float o2 = __shfl_xor_sync(0xffffffffu, bv2, off);
                    int   oi = __shfl_xor_sync(0xffffffffu, bi, off);
                    if (o1 > bv1 || (o1 == bv1 && oi < bi)) {
                        bv2 = fmaxf(bv1, o2); bv1 = o1; bi = oi;
                    } else {
                        bv2 = fmaxf(bv2, o1);
                    }
                }
                if ((lane & 3) == 0) {
                    m1[w * 128 + row] = bv1;
                    m2[w * 128 + row] = bv2;
                    mi[w * 128 + row] = bi;
                }
            }
        }
    }
    __syncthreads();

    // ---- final per-row merge across 8 warps + fp32 loss + flagging
    if (tid < 128) {
        int row = tid;
        float bv1 = m1[row], bv2 = m2[row];
        int   bi  = mi[row];
#pragma unroll
        for (int g = 1; g < 8; g++) {
            float o1 = m1[g * 128 + row];
            float o2 = m2[g * 128 + row];
            if (o1 > bv1) { bv2 = fmaxf(bv1, o2); bv1 = o1; bi = mi[g * 128 + row]; }
            else          { bv2 = fmaxf(bv2, o1); }
        }

        // exact-ish fp32 d = sum (x - e)^2 ; x reconstructed hi+lo (2^-18 rel)
        const __nv_bfloat16* ah = (const __nv_bfloat16*)(smem + SM_AHI + row * RSTRIDE);
        const __nv_bfloat16* al = (const __nv_bfloat16*)(smem + SM_ALO + row * RSTRIDE);
        const float* e = emb + bi * NC;
        float d = 0.f;
#pragma unroll
        for (int c = 0; c < NC; c++) {
            float xv = __bfloat162float(ah[c]) + __bfloat162float(al[c]);
            float t = xv - e[c];
            d += t * t;
        }
        int n = n0 + row;
        g_idx[n]  = bi;
        g_rowd[n] = d;
        atomicAdd(&g_counts[bi], 1.0f);
        if (bv1 - bv2 < THETA) {
            int p = atomicAdd(&g_nflag, 1);
            g_flaglist[p] = n;
        }
    }
}

// ---------------------------------------------------------------------------
// Kernel 2: fp32 fixup for flagged (small-margin) rows. Exact argmin.
// ---------------------------------------------------------------------------
__global__ void __launch_bounds__(128, 8)
vq_fixup(const float* __restrict__ x_in, const float* __restrict__ emb) {
    __shared__ float xrow[64];
    __shared__ float sv[128];
    __shared__ int   si[128];
    int t = threadIdx.x;
    int nf = g_nflag;
    for (int f = blockIdx.x; f < nf; f += gridDim.x) {
        int n = g_flaglist[f];
        int b = n >> 12, hw = n & 4095;
        if (t < 64)
            xrow[t] = x_in[(size_t)b * (NC * NHW) + (size_t)t * NHW + hw];
        __syncthreads();

        float best = -3.4e38f; int bi = 0;
        for (int kk = 0; kk < 4; kk++) {
            int code = kk * 128 + t;
            const float* e = emb + code * NC;
            float dot = 0.f;
#pragma unroll
            for (int c = 0; c < 64; c++) dot += xrow[c] * e[c];
            float s = dot - g_hn[code];
            if (s > best) { best = s; bi = code; }
        }
        sv[t] = best; si[t] = bi;
        __syncthreads();
#pragma unroll
        for (int o = 64; o >= 1; o >>= 1) {
            if (t < o) {
                float a = sv[t], c2 = sv[t + o];
                if (c2 > a || (c2 == a && si[t + o] < si[t])) { sv[t] = c2; si[t] = si[t + o]; }
            }
            __syncthreads();
        }
        if (t == 0) {
            int newi = si[0], old = g_idx[n];
            if (newi != old) {
                atomicAdd(&g_counts[old], -1.0f);
                atomicAdd(&g_counts[newi], 1.0f);
                g_idx[n] = newi;
            }
            // exact d for the final index
            const float* e = emb + newi * NC;
            float d = 0.f;
#pragma unroll
            for (int c = 0; c < 64; c++) { float tt = xrow[c] - e[c]; d += tt * tt; }
            g_rowd[n] = d;
        }
        __syncthreads();
    }
}

// ---------------------------------------------------------------------------
// Kernel 3: gather quantized output (NCHW) + index outputs.
// ---------------------------------------------------------------------------
__global__ void __launch_bounds__(256, 1)
vq_gather(const float* __restrict__ emb, float* __restrict__ out) {
    extern __shared__ float cb[];      // 512 * 65 floats (bank-conflict pad)
    int t = threadIdx.x;
    for (int i = t; i < NK * NC; i += 256)
        cb[(i >> 6) * 65 + (i & 63)] = emb[i];

    int n = blockIdx.x * 256 + t;
    int idx = g_idx[n];
    __syncthreads();

    int b = n >> 12, hw = n & 4095;
    float* qb = out + OFF_Q + (size_t)b * (NC * NHW) + hw;
    const float* cr = cb + idx * 65;
#pragma unroll
    for (int c = 0; c < 64; c++)
        qb[(size_t)c * NHW] = cr[c];   // consecutive threads -> consecutive hw

    float fidx = (float)idx;
    out[OFF_IDX + n]   = fidx;
    out[OFF_CODES + n] = fidx;
}

// ---------------------------------------------------------------------------
// Kernel 4: finalize loss + perplexity (deterministic fixed-order sums)
// ---------------------------------------------------------------------------
__global__ void vq_finalize(float* __restrict__ out) {
    __shared__ float sp[512];
    __shared__ float sl[512];
    int t = threadIdx.x;
    float p = g_counts[t] * (1.0f / (float)NROW);
    sp[t] = p * logf(p + 1e-10f);
    float s = 0.f;
    for (int i = 0; i < NROW / 512; i++) s += g_rowd[i * 512 + t];
    sl[t] = s;
    __syncthreads();
#pragma unroll
    for (int o = 256; o >= 1; o >>= 1) {
        if (t < o) { sp[t] += sp[t + o]; sl[t] += sl[t + o]; }
        __syncthreads();
    }
    if (t == 0) {
        out[OFF_PERP] = expf(-sp[0]);
        out[OFF_LOSS] = 0.25f * sl[0] * (1.0f / 8388608.0f);  // BETA * mean over N*C
    }
}

// ---------------------------------------------------------------------------
// Launch
// ---------------------------------------------------------------------------
extern "C" void kernel_launch(void* const* d_in, const int* in_sizes, int n_in,
                              void* d_out, int out_size) {
    const float* x = (const float*)d_in[0];
    const float* e = (const float*)d_in[1];
    if (n_in >= 2 && in_sizes[0] == NK * NC) {
        const float* tmp = x; x = e; e = tmp;
    }
    float* out = (float*)d_out;

    const int SMEM2 = NK * 65 * (int)sizeof(float);
    cudaFuncSetAttribute(vq_argmin, cudaFuncAttributeMaxDynamicSharedMemorySize, SM_TOTAL);
    cudaFuncSetAttribute(vq_gather, cudaFuncAttributeMaxDynamicSharedMemorySize, SMEM2);

    vq_init<<<1, 512>>>(e);
    vq_argmin<<<NROW / 128, 256, SM_TOTAL>>>(x, e);
    vq_fixup<<<1024, 128>>>(x, e);
    vq_gather<<<NROW / 256, 256, SMEM2>>>(e, out);
    vq_finalize<<<1, 512>>>(out);
}

// round 12
// speedup vs baseline: 1.1042x; 1.1042x over previous
#include <cuda_runtime.h>
#include <cuda_bf16.h>
#include <cstdint>
#include <cstddef>

// Problem: VQ-VAE quantizer
// inputs: (32, 64, 64, 64) f32 NCHW ; emb_weight: (512, 64) f32
// Outputs (f32): loss(1) | quantized(8388608) | encoding_indices(131072) | perplexity(1) | codes(131072)
#define NB   32
#define NC   64
#define NHW  4096
#define NROW 131072
#define NK   512

#define OFF_LOSS  0
#define OFF_Q     1
#define OFF_IDX   8388609
#define OFF_PERP  8519681
#define OFF_CODES 8519682

#define THETA 0.01f

// ---------------------------------------------------------------------------
// PTX helpers — baseline ISA only (ldmatrix sm_75+, mma.sync bf16 sm_80+)
// ---------------------------------------------------------------------------
__device__ __forceinline__ uint32_t smem_to_u32(const void* p) {
    uint32_t a;
    asm("{ .reg .u64 t; cvta.to.shared.u64 t, %1; cvt.u32.u64 %0, t; }" : "=r"(a) : "l"(p));
    return a;
}

#define LDSM_X4(r, a) \
    asm volatile("ldmatrix.sync.aligned.m8n8.x4.shared.b16 {%0,%1,%2,%3}, [%4];" \
        : "=r"((r)[0]), "=r"((r)[1]), "=r"((r)[2]), "=r"((r)[3]) : "r"(a))
#define LDSM_X2(r, a) \
    asm volatile("ldmatrix.sync.aligned.m8n8.x2.shared.b16 {%0,%1}, [%2];" \
        : "=r"((r)[0]), "=r"((r)[1]) : "r"(a))
#define MMA16816(d, a, b) \
    asm volatile("mma.sync.aligned.m16n8k16.row.col.f32.bf16.bf16.f32 " \
        "{%0,%1,%2,%3}, {%4,%5,%6,%7}, {%8,%9}, {%0,%1,%2,%3};" \
        : "+f"((d)[0]), "+f"((d)[1]), "+f"((d)[2]), "+f"((d)[3]) \
        : "r"((a)[0]), "r"((a)[1]), "r"((a)[2]), "r"((a)[3]), \
          "r"((b)[0]), "r"((b)[1]))

// ---------------------------------------------------------------------------
// Scratch
// ---------------------------------------------------------------------------
__device__ int            g_idx[NROW];
__device__ float          g_counts[NK];
__device__ float          g_hn[NK];          // 0.5 * ||e||^2
__device__ float          g_rowd[NROW];      // per-row ||x - e_best||^2 (fp32)
__device__ int            g_flaglist[NROW];
__device__ int            g_nflag;
__device__ __nv_bfloat16  g_ehi[NK * NC];    // codebook bf16 hi, K-major
__device__ __nv_bfloat16  g_elo[NK * NC];    // codebook bf16 lo (residual)

// SMEM layout (bytes). Row stride 144 B (odd multiple of 16) ->
// ldmatrix 8-row access hits distinct bank groups: conflict-free.
#define RSTRIDE   144
#define SM_AHI    0                       // 128 x 144  = 18432
#define SM_ALO    18432                   // 128 x 144
#define SM_BHI    36864                   // 512 x 144  = 73728
#define SM_BLO    110592                  // 512 x 144
#define SM_HN     184320                  // 512 f32    = 2048
#define SM_M1     186368                  // 8 x 128 f32
#define SM_M2     190464
#define SM_MI     194560
#define SM_TOTAL  198656

// ---------------------------------------------------------------------------
// Kernel 0: init — half-norms, bf16 hi/lo codebook, zero counts/flags
// ---------------------------------------------------------------------------
__global__ void vq_init(const float* __restrict__ emb) {
    int t = threadIdx.x;               // 512 threads
    const float4* e = (const float4*)(emb + t * NC);
    float s = 0.f;
#pragma unroll
    for (int i = 0; i < 16; i++) {
        float4 v = e[i];
        s += v.x * v.x + v.y * v.y + v.z * v.z + v.w * v.w;
    }
    g_hn[t] = 0.5f * s;
    g_counts[t] = 0.f;
    if (t == 0) g_nflag = 0;
    for (int i = t; i < NK * NC; i += 512) {
        float v = emb[i];
        __nv_bfloat16 h = __float2bfloat16(v);
        g_ehi[i] = h;
        g_elo[i] = __float2bfloat16(v - __bfloat162float(h));
    }
}

// ---------------------------------------------------------------------------
// Kernel 1: mma.sync argmin. CTA = 128 rows x 512 codes, 256 threads (8 warps).
// Warp w owns codes [w*64, w*64+64). B-hi fragments hoisted to registers ONCE
// (64 regs/warp); B-lo LDSM is overlapped behind 4 independent MMAs.
// bf16 hi/lo split: D = xh*eh + xh*el + xl*eh (fp32 accum in registers).
// ---------------------------------------------------------------------------
__global__ void __launch_bounds__(256, 1)
vq_argmin(const float* __restrict__ x_in, const float* __restrict__ emb) {
    extern __shared__ char smem[];
    const uint32_t sb = smem_to_u32(smem);
    float* hn_s = (float*)(smem + SM_HN);
    float* m1   = (float*)(smem + SM_M1);
    float* m2   = (float*)(smem + SM_M2);
    int*   mi   = (int*)  (smem + SM_MI);

    const int tid  = threadIdx.x;
    const int w    = tid >> 5;
    const int lane = tid & 31;
    const int n0   = blockIdx.x * 128;
    const int b    = n0 >> 12;
    const int hw0  = n0 & 4095;

    // ---- prologue: x tile -> A hi/lo (row m, col c; 144B row stride)
    const float* xbase = x_in + (size_t)b * (NC * NHW) + hw0;
    for (int i = tid; i < 64 * 128; i += 256) {
        int c = i >> 7, m = i & 127;                    // coalesced over m
        float v = xbase[(size_t)c * NHW + m];
        __nv_bfloat16 h = __float2bfloat16(v);
        __nv_bfloat16 l = __float2bfloat16(v - __bfloat162float(h));
        *(__nv_bfloat16*)(smem + SM_AHI + m * RSTRIDE + c * 2) = h;
        *(__nv_bfloat16*)(smem + SM_ALO + m * RSTRIDE + c * 2) = l;
    }
    // ---- codebook hi/lo -> B tiles (row = code, 144B stride), 4B words
    {
        const uint32_t* ehi = (const uint32_t*)g_ehi;
        const uint32_t* elo = (const uint32_t*)g_elo;
        for (int i = tid; i < NK * NC / 2; i += 256) {
            int code = i >> 5, cw = i & 31;
            *(uint32_t*)(smem + SM_BHI + code * RSTRIDE + cw * 4) = ehi[i];
            *(uint32_t*)(smem + SM_BLO + code * RSTRIDE + cw * 4) = elo[i];
        }
    }
    for (int i = tid; i < NK; i += 256) hn_s[i] = g_hn[i];
    __syncthreads();

    const uint32_t a_lane_off = (uint32_t)((lane & 15) * RSTRIDE + (lane >> 4) * 16);
    const uint32_t b_lane_off = (uint32_t)((w * 64 + (lane & 7)) * RSTRIDE + ((lane >> 3) & 1) * 16);
    const uint32_t bb_hi = sb + SM_BHI + b_lane_off;
    const uint32_t bb_lo = sb + SM_BLO + b_lane_off;

    // ---- hoist ALL B-hi fragments into registers (loaded exactly once)
    uint32_t bh[8][4][2];                 // [nt][k][reg] = 64 regs
#pragma unroll
    for (int nt = 0; nt < 8; nt++)
#pragma unroll
        for (int k = 0; k < 4; k++)
            LDSM_X2(bh[nt][k], bb_hi + (uint32_t)(nt * 8 * RSTRIDE) + k * 32);

    // ---- main: 4 passes of 32 rows (2 m16-tiles); per (k,nt): 6 MMA, 1 LDSM
    for (int mt2 = 0; mt2 < 4; mt2++) {
        float acc[2][8][4];
#pragma unroll
        for (int p = 0; p < 2; p++)
#pragma unroll
            for (int nt = 0; nt < 8; nt++)
#pragma unroll
                for (int c = 0; c < 4; c++) acc[p][nt][c] = 0.f;

        const uint32_t abh = sb + SM_AHI + (uint32_t)(mt2 * 32 * RSTRIDE) + a_lane_off;
        const uint32_t abl = sb + SM_ALO + (uint32_t)(mt2 * 32 * RSTRIDE) + a_lane_off;
#pragma unroll
        for (int k = 0; k < 4; k++) {
            uint32_t a0h[4], a1h[4], a0l[4], a1l[4];
            LDSM_X4(a0h, abh + k * 32);
            LDSM_X4(a1h, abh + 16 * RSTRIDE + k * 32);
            LDSM_X4(a0l, abl + k * 32);
            LDSM_X4(a1l, abl + 16 * RSTRIDE + k * 32);
#pragma unroll
            for (int nt = 0; nt < 8; nt++) {
                uint32_t blf[2];
                LDSM_X2(blf, bb_lo + (uint32_t)(nt * 8 * RSTRIDE) + k * 32);
                // 4 register-B MMAs cover the LDSM latency
                MMA16816(acc[0][nt], a0h, bh[nt][k]);
                MMA16816(acc[1][nt], a1h, bh[nt][k]);
                MMA16816(acc[0][nt], a0l, bh[nt][k]);
                MMA16816(acc[1][nt], a1l, bh[nt][k]);
                MMA16816(acc[0][nt], a0h, blf);
                MMA16816(acc[1][nt], a1h, blf);
            }
        }

        // ---- epilogue for rows [mt2*32, mt2*32+32)
#pragma unroll
        for (int p = 0; p < 2; p++) {
#pragma unroll
            for (int h = 0; h < 2; h++) {
                int row = mt2 * 32 + p * 16 + h * 8 + (lane >> 2);
                float bv1 = -3.4e38f, bv2 = -3.4e38f;
                int bi = 0;
#pragma unroll
                for (int nt = 0; nt < 8; nt++) {
                    int code = w * 64 + nt * 8 + 2 * (lane & 3);
                    float v0 = acc[p][nt][h * 2 + 0] - hn_s[code];
                    float v1 = acc[p][nt][h * 2 + 1] - hn_s[code + 1];
                    if (v0 > bv1) { bv2 = bv1; bv1 = v0; bi = code; }
                    else if (v0 > bv2) bv2 = v0;
                    if (v1 > bv1) { bv2 = bv1; bv1 = v1; bi = code + 1; }
                    else if (v1 > bv2) bv2 = v1;
                }
#pragma unroll
                for (int off = 1; off <= 2; off <<= 1) {
                    float o1 = __shfl_xor_sync(0xffffffffu, bv1, off);
                    float o2 = __shfl_xor_sync(0xffffffffu, bv2, off);
                    int   oi = __shfl_xor_sync(0xffffffffu, bi, off);
                    if (o1 > bv1 || (o1 == bv1 && oi < bi)) {
                        bv2 = fmaxf(bv1, o2); bv1 = o1; bi = oi;
                    } else {
                        bv2 = fmaxf(bv2, o1);
                    }
                }
                if ((lane & 3) == 0) {
                    m1[w * 128 + row] = bv1;
                    m2[w * 128 + row] = bv2;
                    mi[w * 128 + row] = bi;
                }
            }
        }
    }
    __syncthreads();

    // ---- final per-row merge across 8 warps + fp32 loss + flagging
    if (tid < 128) {
        int row = tid;
        float bv1 = m1[row], bv2 = m2[row];
        int   bi  = mi[row];
#pragma unroll
        for (int g = 1; g < 8; g++) {
            float o1 = m1[g * 128 + row];
            float o2 = m2[g * 128 + row];
            if (o1 > bv1) { bv2 = fmaxf(bv1, o2); bv1 = o1; bi = mi[g * 128 + row]; }
            else          { bv2 = fmaxf(bv2, o1); }
        }

        // fp32 d = sum (x - e)^2 ; x reconstructed hi+lo (2^-18 rel)
        const __nv_bfloat16* ah = (const __nv_bfloat16*)(smem + SM_AHI + row * RSTRIDE);
        const __nv_bfloat16* al = (const __nv_bfloat16*)(smem + SM_ALO + row * RSTRIDE);
        const float* e = emb + bi * NC;
        float d = 0.f;
#pragma unroll
        for (int c = 0; c < NC; c++) {
            float xv = __bfloat162float(ah[c]) + __bfloat162float(al[c]);
            float t = xv - e[c];
            d += t * t;
        }
        int n = n0 + row;
        g_idx[n]  = bi;
        g_rowd[n] = d;
        atomicAdd(&g_counts[bi], 1.0f);
        if (bv1 - bv2 < THETA) {
            int p = atomicAdd(&g_nflag, 1);
            g_flaglist[p] = n;
        }
    }
}

// ---------------------------------------------------------------------------
// Kernel 2: fp32 fixup for flagged (small-margin) rows. Exact argmin.
// ---------------------------------------------------------------------------
__global__ void __launch_bounds__(128, 8)
vq_fixup(const float* __restrict__ x_in, const float* __restrict__ emb) {
    __shared__ float xrow[64];
    __shared__ float sv[128];
    __shared__ int   si[128];
    int t = threadIdx.x;
    int nf = g_nflag;
    for (int f = blockIdx.x; f < nf; f += gridDim.x) {
        int n = g_flaglist[f];
        int b = n >> 12, hw = n & 4095;
        if (t < 64)
            xrow[t] = x_in[(size_t)b * (NC * NHW) + (size_t)t * NHW + hw];
        __syncthreads();

        float best = -3.4e38f; int bi = 0;
        for (int kk = 0; kk < 4; kk++) {
            int code = kk * 128 + t;
            const float* e = emb + code * NC;
            float dot = 0.f;
#pragma unroll
            for (int c = 0; c < 64; c++) dot += xrow[c] * e[c];
            float s = dot - g_hn[code];
            if (s > best) { best = s; bi = code; }
        }
        sv[t] = best; si[t] = bi;
        __syncthreads();
#pragma unroll
        for (int o = 64; o >= 1; o >>= 1) {
            if (t < o) {
                float a = sv[t], c2 = sv[t + o];
                if (c2 > a || (c2 == a && si[t + o] < si[t])) { sv[t] = c2; si[t] = si[t + o]; }
            }
            __syncthreads();
        }
        if (t == 0) {
            int newi = si[0], old = g_idx[n];
            if (newi != old) {
                atomicAdd(&g_counts[old], -1.0f);
                atomicAdd(&g_counts[newi], 1.0f);
                g_idx[n] = newi;
            }
            const float* e = emb + newi * NC;
            float d = 0.f;
#pragma unroll
            for (int c = 0; c < 64; c++) { float tt = xrow[c] - e[c]; d += tt * tt; }
            g_rowd[n] = d;
        }
        __syncthreads();
    }
}

// ---------------------------------------------------------------------------
// Kernel 3: gather quantized output (NCHW) + index outputs.
// NO smem staging (that capped occupancy at 12.5% and cost 43us):
// codebook is 131KB, L2-resident; read float4 via __ldg, write coalesced.
// ---------------------------------------------------------------------------
__global__ void __launch_bounds__(256)
vq_gather(const float* __restrict__ emb, float* __restrict__ out) {
    int n = blockIdx.x * 256 + threadIdx.x;
    int idx = g_idx[n];
    const float4* cr = (const float4*)(emb + (size_t)idx * NC);

    int b = n >> 12, hw = n & 4095;
    float* qb = out + OFF_Q + (size_t)b * (NC * NHW) + hw;
#pragma unroll
    for (int q = 0; q < 16; q++) {
        float4 v = __ldg(cr + q);
        qb[(size_t)(4 * q + 0) * NHW] = v.x;   // consecutive threads -> consecutive hw
        qb[(size_t)(4 * q + 1) * NHW] = v.y;
        qb[(size_t)(4 * q + 2) * NHW] = v.z;
        qb[(size_t)(4 * q + 3) * NHW] = v.w;
    }
    float fidx = (float)idx;
    out[OFF_IDX + n]   = fidx;
    out[OFF_CODES + n] = fidx;
}

// ---------------------------------------------------------------------------
// Kernel 4: finalize loss + perplexity (deterministic fixed-order sums)
// ---------------------------------------------------------------------------
__global__ void vq_finalize(float* __restrict__ out) {
    __shared__ float sp[512];
    __shared__ float sl[512];
    int t = threadIdx.x;
    float p = g_counts[t] * (1.0f / (float)NROW);
    sp[t] = p * logf(p + 1e-10f);
    float s = 0.f;
    for (int i = 0; i < NROW / 512; i++) s += g_rowd[i * 512 + t];
    sl[t] = s;
    __syncthreads();
#pragma unroll
    for (int o = 256; o >= 1; o >>= 1) {
        if (t < o) { sp[t] += sp[t + o]; sl[t] += sl[t + o]; }
        __syncthreads();
    }
    if (t == 0) {
        out[OFF_PERP] = expf(-sp[0]);
        out[OFF_LOSS] = 0.25f * sl[0] * (1.0f / 8388608.0f);  // BETA * mean over N*C
    }
}

// ---------------------------------------------------------------------------
// Launch
// ---------------------------------------------------------------------------
extern "C" void kernel_launch(void* const* d_in, const int* in_sizes, int n_in,
                              void* d_out, int out_size) {
    const float* x = (const float*)d_in[0];
    const float* e = (const float*)d_in[1];
    if (n_in >= 2 && in_sizes[0] == NK * NC) {
        const float* tmp = x; x = e; e = tmp;
    }
    float* out = (float*)d_out;

    cudaFuncSetAttribute(vq_argmin, cudaFuncAttributeMaxDynamicSharedMemorySize, SM_TOTAL);

    vq_init<<<1, 512>>>(e);
    vq_argmin<<<NROW / 128, 256, SM_TOTAL>>>(x, e);
    vq_fixup<<<1024, 128>>>(x, e);
    vq_gather<<<NROW / 256, 256>>>(e, out);
    vq_finalize<<<1, 512>>>(out);
}